// round 8
// baseline (speedup 1.0000x reference)
#include <cuda_runtime.h>
#include <cuda_fp16.h>
#include <math.h>
#include <stdint.h>

// Problem constants: N=100000, E=1600000, Cin=64, H=16, Cout=16, K=5
#define NCAP 100096            // multiple of 128 (and < 98*1024)
#define ECAP 1605632
#define NB 98                  // scan blocks = ceil(NCAP/1024)

// Scratch (allocation-free contract).
__device__ __half g_y[(size_t)NCAP * 400];     // per-kernel products, fp16
__device__ float  g_h[(size_t)NCAP * 16];      // layer-1 output (post ReLU)
__device__ float  g_rt[(size_t)NCAP * 16];     // x @ root + bias (per layer)
__device__ uint32_t g_B1[52 * 8 * 64];         // tf32 B fragments, layer 1
__device__ uint32_t g_B2[52 * 2 * 64];         // tf32 B fragments, layer 2
// CSR build (by dst)
__device__ int   g_cnt[NCAP];
__device__ int   g_scan[NCAP];
__device__ int   g_blk[NB];
__device__ int   g_off[NCAP + 1];
__device__ int   g_cur[NCAP];
__device__ uint4 g_es[ECAP];                   // packed edge: {src, p0, p1, 0}

__device__ __forceinline__ uint32_t f2tf32(float f) {
    uint32_t o;
    asm("cvt.rna.tf32.f32 %0, %1;" : "=r"(o) : "f"(f));
    return o;
}
__device__ __forceinline__ void mma_tf32(float* c, const uint32_t* a, uint32_t b0, uint32_t b1) {
    asm volatile("mma.sync.aligned.m16n8k8.row.col.f32.tf32.tf32.f32 "
                 "{%0,%1,%2,%3}, {%4,%5,%6,%7}, {%8,%9}, {%0,%1,%2,%3};"
                 : "+f"(c[0]), "+f"(c[1]), "+f"(c[2]), "+f"(c[3])
                 : "r"(a[0]), "r"(a[1]), "r"(a[2]), "r"(a[3]), "r"(b0), "r"(b1));
}
__device__ __forceinline__ void cp_async16(uint32_t saddr, const void* g) {
    asm volatile("cp.async.cg.shared.global [%0], [%1], 16;" :: "r"(saddr), "l"(g));
}
#define CP_COMMIT() asm volatile("cp.async.commit_group;" ::: "memory")
#define CP_WAIT1()  asm volatile("cp.async.wait_group 1;" ::: "memory")
__device__ __forceinline__ uint32_t smem_u32(const void* p) {
    uint32_t a;
    asm("{ .reg .u64 t; cvta.to.shared.u64 t, %1; cvt.u32.u64 %0, t; }" : "=r"(a) : "l"(p));
    return a;
}

// ---------------- CSR build ----------------
__global__ void zerocnt_kernel() {
    int i = blockIdx.x * blockDim.x + threadIdx.x;
    if (i < NCAP) g_cnt[i] = 0;
}
__global__ void hist_kernel(const int* __restrict__ dst, int E) {
    int i = blockIdx.x * blockDim.x + threadIdx.x;
    if (i < E) atomicAdd(&g_cnt[dst[i]], 1);
}
__global__ void scan1_kernel() {
    __shared__ int s[1024];
    int i = blockIdx.x * 1024 + threadIdx.x;
    int v = (i < NCAP) ? g_cnt[i] : 0;
    s[threadIdx.x] = v;
    __syncthreads();
    for (int d = 1; d < 1024; d <<= 1) {
        int x = (threadIdx.x >= d) ? s[threadIdx.x - d] : 0;
        __syncthreads();
        s[threadIdx.x] += x;
        __syncthreads();
    }
    if (i < NCAP) g_scan[i] = s[threadIdx.x];   // inclusive
    if (threadIdx.x == 1023) g_blk[blockIdx.x] = s[1023];
}
__global__ void scan2_kernel() {
    if (threadIdx.x == 0 && blockIdx.x == 0) {
        int run = 0;
        for (int b = 0; b < NB; b++) { int t = g_blk[b]; g_blk[b] = run; run += t; }
        g_off[NCAP] = run;
    }
}
__global__ void scan3_kernel() {
    int i = blockIdx.x * blockDim.x + threadIdx.x;
    if (i >= NCAP) return;
    int off = g_scan[i] - g_cnt[i] + g_blk[i >> 10];   // exclusive
    g_off[i] = off;
    g_cur[i] = off;
}
__global__ void fill_kernel(const int* __restrict__ src, const int* __restrict__ dst,
                            const float* __restrict__ pseudo, int E) {
    int e = blockIdx.x * blockDim.x + threadIdx.x;
    if (e >= E) return;
    int d = __ldg(dst + e);
    int p = atomicAdd(&g_cur[d], 1);
    float2 ps = __ldg(reinterpret_cast<const float2*>(pseudo) + e);
    uint4 v;
    v.x = (uint32_t)__ldg(src + e);
    v.y = __float_as_uint(ps.x);
    v.z = __float_as_uint(ps.y);
    v.w = 0u;
    g_es[p] = v;
}

// ---------------- B fragment prep ----------------
// Logical B[n=0..415][k]: n<400 -> W[(kk*CIN+k)*16+o] (kk=n>>4, o=n&15); n>=400 -> root[k*16+(n-400)].
template<int CIN, int KSTEPS>
__global__ void prepB_kernel(const float* __restrict__ W, const float* __restrict__ root,
                             uint32_t* __restrict__ Bg) {
    int idx = blockIdx.x * blockDim.x + threadIdx.x;
    if (idx >= 52 * KSTEPS * 64) return;
    int ntile = idx / (KSTEPS * 64);
    int rem = idx % (KSTEPS * 64);
    int ks = rem / 64;
    int q = rem % 64;
    int lane = q >> 1;
    int reg = q & 1;
    int n = ntile * 8 + (lane >> 2);
    int k = ks * 8 + (lane & 3) + reg * 4;
    float v = 0.0f;
    if (k < CIN) {
        if (n < 400) {
            int kk = n >> 4, o = n & 15;
            v = W[(kk * CIN + k) * 16 + o];
        } else {
            v = root[k * 16 + (n - 400)];
        }
    }
    Bg[idx] = f2tf32(v);
}

// ---------------- HMMA tf32 GEMM ----------------
// Per CTA: M=128 nodes, N=416 (400 y cols fp16 + 16 rt cols fp32+bias).
// LAYER=1: A = Xin (K=64). LAYER=2: A = g_h (K=16).
template<int LAYER, int KSTEPS>
__global__ void __launch_bounds__(128) gemm_kernel(const float* __restrict__ Xin,
                                                   const uint32_t* __restrict__ Bg,
                                                   const float* __restrict__ bias, int N) {
    constexpr int KC = KSTEPS * 8;
    constexpr int AP = KC + 4;
    constexpr int CHUNK_U32 = 4 * KSTEPS * 64;
    extern __shared__ uint32_t sm[];
    uint32_t* Asm = sm;                      // [128][AP]
    uint32_t* Bbuf = sm + 128 * AP;          // [2][CHUNK_U32]
    const uint32_t bbase = smem_u32(Bbuf);

    const int tid = threadIdx.x;
    const int wid = tid >> 5;
    const int lane = tid & 31;
    const int gID = lane >> 2;
    const int tig = lane & 3;
    const int n0 = blockIdx.x * 128;

    // Prefetch chunk 0 B.
    {
        constexpr int PT = CHUNK_U32 / (128 * 4);
        #pragma unroll
        for (int i = 0; i < PT; i++)
            cp_async16(bbase + (tid + i * 128) * 16, (const char*)Bg + (tid + i * 128) * 16);
        CP_COMMIT();
    }

    // Build this thread's A row.
    {
        const int n = n0 + tid;
        const float4* xr = (LAYER == 1)
            ? reinterpret_cast<const float4*>(Xin + (size_t)n * 64)
            : reinterpret_cast<const float4*>(g_h + (size_t)n * 16);
        #pragma unroll
        for (int c = 0; c < KC / 4; c++) {
            float4 f = (n < N) ? __ldg(xr + c) : make_float4(0.f, 0.f, 0.f, 0.f);
            Asm[tid * AP + 4 * c]     = f2tf32(f.x);
            Asm[tid * AP + 4 * c + 1] = f2tf32(f.y);
            Asm[tid * AP + 4 * c + 2] = f2tf32(f.z);
            Asm[tid * AP + 4 * c + 3] = f2tf32(f.w);
        }
    }
    __syncthreads();

    // A fragments: [mtile][kstep][4]
    uint32_t a[2][KSTEPS][4];
    #pragma unroll
    for (int mt = 0; mt < 2; mt++) {
        int r0 = wid * 32 + mt * 16 + gID;
        #pragma unroll
        for (int ks = 0; ks < KSTEPS; ks++) {
            a[mt][ks][0] = Asm[r0 * AP + ks * 8 + tig];
            a[mt][ks][1] = Asm[(r0 + 8) * AP + ks * 8 + tig];
            a[mt][ks][2] = Asm[r0 * AP + ks * 8 + tig + 4];
            a[mt][ks][3] = Asm[(r0 + 8) * AP + ks * 8 + tig + 4];
        }
    }

    #pragma unroll 1
    for (int chunk = 0; chunk < 13; chunk++) {
        if (chunk + 1 < 13) {
            constexpr int PT = CHUNK_U32 / (128 * 4);
            uint32_t dstS = bbase + ((chunk + 1) & 1) * (CHUNK_U32 * 4);
            const char* srcG = (const char*)(Bg + (size_t)(chunk + 1) * CHUNK_U32);
            #pragma unroll
            for (int i = 0; i < PT; i++)
                cp_async16(dstS + (tid + i * 128) * 16, srcG + (tid + i * 128) * 16);
        }
        CP_COMMIT();
        CP_WAIT1();
        __syncthreads();

        const uint32_t* bb = Bbuf + (chunk & 1) * CHUNK_U32;
        float c[2][4][4];
        #pragma unroll
        for (int mt = 0; mt < 2; mt++)
            #pragma unroll
            for (int nt = 0; nt < 4; nt++)
                #pragma unroll
                for (int r = 0; r < 4; r++) c[mt][nt][r] = 0.0f;

        #pragma unroll
        for (int ks = 0; ks < KSTEPS; ks++)
            #pragma unroll
            for (int nt = 0; nt < 4; nt++) {
                uint2 b = *reinterpret_cast<const uint2*>(bb + (nt * KSTEPS + ks) * 64 + lane * 2);
                mma_tf32(c[0][nt], a[0][ks], b.x, b.y);
                mma_tf32(c[1][nt], a[1][ks], b.x, b.y);
            }
        __syncthreads();

        #pragma unroll
        for (int mt = 0; mt < 2; mt++)
            #pragma unroll
            for (int nt = 0; nt < 4; nt++) {
                int col = chunk * 32 + nt * 8 + tig * 2;
                int row0 = n0 + wid * 32 + mt * 16 + gID;
                int row1 = row0 + 8;
                float* cc = c[mt][nt];
                if (col < 400) {
                    if (row0 < N)
                        *reinterpret_cast<__half2*>(g_y + (size_t)row0 * 400 + col) =
                            __floats2half2_rn(cc[0], cc[1]);
                    if (row1 < N)
                        *reinterpret_cast<__half2*>(g_y + (size_t)row1 * 400 + col) =
                            __floats2half2_rn(cc[2], cc[3]);
                } else {
                    int o = col - 400;
                    float bv0 = __ldg(bias + o), bv1 = __ldg(bias + o + 1);
                    if (row0 < N) {
                        g_rt[(size_t)row0 * 16 + o] = cc[0] + bv0;
                        g_rt[(size_t)row0 * 16 + o + 1] = cc[1] + bv1;
                    }
                    if (row1 < N) {
                        g_rt[(size_t)row1 * 16 + o] = cc[2] + bv0;
                        g_rt[(size_t)row1 * 16 + o + 1] = cc[3] + bv1;
                    }
                }
            }
    }
}

// ---------------- CSR gather pass: warp per dst node ----------------
// Lane layout: eslot(2b) | corner c(2b) | half q(1b). 4 edges per round.
// msg = sum_e sum_c w_c * y[src_e, k_c]; out = msg/max(deg,1) + rt  (+ReLU for layer 1).
template<int LAYER>
__global__ void __launch_bounds__(256) gather_kernel(float* __restrict__ out, int N) {
    const int gw = (blockIdx.x * blockDim.x + threadIdx.x) >> 5;
    if (gw >= N) return;
    const int n = gw;
    const int lane = threadIdx.x & 31;
    const int eslot = lane >> 3;
    const int c = (lane >> 1) & 3;
    const int q = lane & 1;

    const int beg = __ldg(g_off + n);
    const int end = __ldg(g_off + n + 1);
    const int deg = end - beg;

    float acc[8] = {0.f, 0.f, 0.f, 0.f, 0.f, 0.f, 0.f, 0.f};

    for (int e = beg + eslot; e < end; e += 4) {
        uint4 ed = __ldg(g_es + e);
        int s = (int)ed.x;
        float p0 = __uint_as_float(ed.y);
        float p1 = __uint_as_float(ed.z);
        float v0 = p0 * 4.0f, v1 = p1 * 4.0f;
        float fl0 = floorf(v0), fl1 = floorf(v1);
        float f0 = v0 - fl0, f1 = v1 - fl1;
        int i0 = (int)fl0, i1 = (int)fl1;
        int i0b = i0 + 1; if (i0b >= 5) i0b = 0;
        int i1b = i1 + 1; if (i1b >= 5) i1b = 0;
        int i0s = (c & 1) ? i0b : i0;
        int i1s = (c & 2) ? i1b : i1;
        float w0 = (c & 1) ? f0 : (1.0f - f0);
        float w1 = (c & 2) ? f1 : (1.0f - f1);
        float w = w0 * w1;

        const uint4* yp = reinterpret_cast<const uint4*>(g_y + (size_t)s * 400)
                          + (i1s * 5 + i0s) * 2 + q;
        uint4 cv = __ldg(yp);
        #pragma unroll
        for (int j = 0; j < 4; j++) {
            float2 f = __half22float2(*reinterpret_cast<const __half2*>(((const unsigned*)&cv) + j));
            acc[2 * j]     += w * f.x;
            acc[2 * j + 1] += w * f.y;
        }
    }

    // Fold 16 lanes with same q (xor over bits 1..4 keeps q fixed).
    #pragma unroll
    for (int o = 2; o <= 16; o <<= 1)
        #pragma unroll
        for (int j = 0; j < 8; j++)
            acc[j] += __shfl_xor_sync(0xFFFFFFFFu, acc[j], o);

    if (lane < 2) {
        float scale = 1.0f / fmaxf((float)deg, 1.0f);
        const float* rtp = g_rt + (size_t)n * 16 + lane * 8;
        float o[8];
        #pragma unroll
        for (int j = 0; j < 8; j++) {
            o[j] = acc[j] * scale + __ldg(rtp + j);
            if (LAYER == 1) o[j] = o[j] > 0.f ? o[j] : 0.f;
        }
        float* dp = (LAYER == 1) ? (g_h + (size_t)n * 16 + lane * 8)
                                 : (out + (size_t)n * 16 + lane * 8);
        reinterpret_cast<float4*>(dp)[0] = make_float4(o[0], o[1], o[2], o[3]);
        reinterpret_cast<float4*>(dp)[1] = make_float4(o[4], o[5], o[6], o[7]);
    }
}

extern "C" void kernel_launch(void* const* d_in, const int* in_sizes, int n_in,
                              void* d_out, int out_size) {
    const float* x      = (const float*)d_in[0];
    const int*   ei     = (const int*)  d_in[1];
    const float* pseudo = (const float*)d_in[2];
    const float* W1     = (const float*)d_in[3];
    const float* root1  = (const float*)d_in[4];
    const float* b1     = (const float*)d_in[5];
    const float* W2     = (const float*)d_in[6];
    const float* root2  = (const float*)d_in[7];
    const float* b2     = (const float*)d_in[8];
    float* out = (float*)d_out;

    int N = in_sizes[0] / 64;
    int E = in_sizes[1] / 2;
    if (N > NCAP) N = NCAP;
    if (E > ECAP) E = ECAP;
    const int* src = ei;
    const int* dst = ei + E;

    const int smem1 = 51200, smem2 = 14336;
    static uint32_t *B1p = nullptr, *B2p = nullptr;
    if (!B1p) {
        cudaGetSymbolAddress((void**)&B1p, g_B1);
        cudaGetSymbolAddress((void**)&B2p, g_B2);
        cudaFuncSetAttribute((const void*)gemm_kernel<1, 8>,
                             cudaFuncAttributeMaxDynamicSharedMemorySize, smem1);
        cudaFuncSetAttribute((const void*)gemm_kernel<2, 2>,
                             cudaFuncAttributeMaxDynamicSharedMemorySize, smem2);
    }

    int gemmGrid = (N + 127) / 128;
    int eGrid = (E + 255) / 256;
    int nGrid = (NCAP + 255) / 256;
    int gatherGrid = (N * 32 + 255) / 256;

    // ---- CSR build (by dst) ----
    zerocnt_kernel<<<nGrid, 256>>>();
    hist_kernel<<<eGrid, 256>>>(dst, E);
    scan1_kernel<<<NB, 1024>>>();
    scan2_kernel<<<1, 32>>>();
    scan3_kernel<<<nGrid, 256>>>();
    fill_kernel<<<eGrid, 256>>>(src, dst, pseudo, E);

    // ---- Weight prep ----
    prepB_kernel<64, 8><<<(52 * 8 * 64 + 255) / 256, 256>>>(W1, root1, B1p);
    prepB_kernel<16, 2><<<(52 * 2 * 64 + 255) / 256, 256>>>(W2, root2, B2p);

    // ---- Layer 1 ----
    gemm_kernel<1, 8><<<gemmGrid, 128, smem1>>>(x, B1p, b1, N);
    gather_kernel<1><<<gatherGrid, 256>>>(nullptr, N);
    // ---- Layer 2 ----
    gemm_kernel<2, 2><<<gemmGrid, 128, smem2>>>(nullptr, B2p, b2, N);
    gather_kernel<2><<<gatherGrid, 256>>>(out, N);
}

// round 9
// speedup vs baseline: 1.2575x; 1.2575x over previous
#include <cuda_runtime.h>
#include <cuda_fp16.h>
#include <math.h>
#include <stdint.h>

// Problem constants: N=100000, E=1600000, Cin=64, H=16, Cout=16, K=5
#define NCAP 100096   // multiple of 128

// Scratch (allocation-free contract).
__device__ __half g_y[(size_t)NCAP * 400];     // per-kernel products, fp16
__device__ float  g_agg[(size_t)NCAP * 16];    // per-layer aggregation
__device__ float  g_deg[NCAP];                 // in-degree
__device__ float  g_rt[(size_t)NCAP * 16];     // x @ root + bias (per layer)
// B in tf32 fragment layout: [ntile(52)][kstep][lane(32)*2] u32
__device__ uint32_t g_B1[52 * 8 * 64];
__device__ uint32_t g_B2[52 * 2 * 64];

__device__ __forceinline__ void red_add_v4(float* a, float x, float y, float z, float w) {
    asm volatile("red.global.add.v4.f32 [%0], {%1, %2, %3, %4};"
                 :: "l"(a), "f"(x), "f"(y), "f"(z), "f"(w) : "memory");
}
__device__ __forceinline__ uint32_t f2tf32(float f) {
    uint32_t o;
    asm("cvt.rna.tf32.f32 %0, %1;" : "=r"(o) : "f"(f));
    return o;
}
__device__ __forceinline__ void mma_tf32(float* c, const uint32_t* a, uint32_t b0, uint32_t b1) {
    asm volatile("mma.sync.aligned.m16n8k8.row.col.f32.tf32.tf32.f32 "
                 "{%0,%1,%2,%3}, {%4,%5,%6,%7}, {%8,%9}, {%0,%1,%2,%3};"
                 : "+f"(c[0]), "+f"(c[1]), "+f"(c[2]), "+f"(c[3])
                 : "r"(a[0]), "r"(a[1]), "r"(a[2]), "r"(a[3]), "r"(b0), "r"(b1));
}
__device__ __forceinline__ void cp_async16(uint32_t saddr, const void* g) {
    asm volatile("cp.async.cg.shared.global [%0], [%1], 16;" :: "r"(saddr), "l"(g));
}
#define CP_COMMIT() asm volatile("cp.async.commit_group;" ::: "memory")
#define CP_WAIT1()  asm volatile("cp.async.wait_group 1;" ::: "memory")
__device__ __forceinline__ uint32_t smem_u32(const void* p) {
    uint32_t a;
    asm("{ .reg .u64 t; cvta.to.shared.u64 t, %1; cvt.u32.u64 %0, t; }" : "=r"(a) : "l"(p));
    return a;
}

// Build tf32 B fragments. Logical B[n=0..415][k]: n<400 -> W[(kk*CIN+k)*16+o]
// (kk=n>>4, o=n&15); n>=400 -> root[k*16+(n-400)].
template<int CIN, int KSTEPS>
__global__ void prepB_kernel(const float* __restrict__ W, const float* __restrict__ root,
                             uint32_t* __restrict__ Bg) {
    int idx = blockIdx.x * blockDim.x + threadIdx.x;
    if (idx >= 52 * KSTEPS * 64) return;
    int ntile = idx / (KSTEPS * 64);
    int rem = idx % (KSTEPS * 64);
    int ks = rem / 64;
    int q = rem % 64;
    int lane = q >> 1;
    int reg = q & 1;
    int n = ntile * 8 + (lane >> 2);
    int k = ks * 8 + (lane & 3) + reg * 4;
    float v = 0.0f;
    if (k < CIN) {
        if (n < 400) {
            int kk = n >> 4, o = n & 15;
            v = W[(kk * CIN + k) * 16 + o];
        } else {
            v = root[k * 16 + (n - 400)];
        }
    }
    Bg[idx] = f2tf32(v);
}

// HMMA tf32 GEMM + fusions. Per CTA: M=128 nodes, N=416; 256 threads, 8 warps,
// ONE m16 tile per warp (lower regs -> 3 CTAs/SM, shorter MMA chains).
// LAYER=1: A = Xin; also zero g_agg + g_deg for its rows (before edge pass 1).
// LAYER=2: A = relu(agg/max(deg,1) + rt) inline; then re-zero g_agg.
template<int LAYER, int KSTEPS>
__global__ void __launch_bounds__(256) gemm_kernel(const float* __restrict__ Xin,
                                                   const uint32_t* __restrict__ Bg,
                                                   const float* __restrict__ bias, int N) {
    constexpr int KC = KSTEPS * 8;          // real K (64 or 16)
    constexpr int AP = KC + 4;              // A row pitch (u32)
    constexpr int CHUNK_U32 = 4 * KSTEPS * 64;
    extern __shared__ uint32_t sm[];
    uint32_t* Asm = sm;                      // [128][AP]
    uint32_t* Bbuf = sm + 128 * AP;          // [2][CHUNK_U32]
    const uint32_t bbase = smem_u32(Bbuf);

    const int tid = threadIdx.x;
    const int wid = tid >> 5;
    const int lane = tid & 31;
    const int gID = lane >> 2;
    const int tig = lane & 3;
    const int n0 = blockIdx.x * 128;

    // Prefetch chunk 0 B (CHUNK bytes = CHUNK_U32*4; 16B per load).
    {
        constexpr int NLD = CHUNK_U32 / 4;
        for (int i = tid; i < NLD; i += 256)
            cp_async16(bbase + i * 16, (const char*)Bg + i * 16);
        CP_COMMIT();
    }

    // Threads 0..127 each own row n0+tid: build A row + fused per-node work.
    if (tid < 128) {
        const int n = n0 + tid;
        float4* aggp = reinterpret_cast<float4*>(g_agg + (size_t)n * 16);
        if (LAYER == 1) {
            const float4* xr = reinterpret_cast<const float4*>(Xin + (size_t)n * 64);
            #pragma unroll
            for (int c = 0; c < KC / 4; c++) {
                float4 f = (n < N) ? __ldg(xr + c) : make_float4(0.f, 0.f, 0.f, 0.f);
                Asm[tid * AP + 4 * c]     = f2tf32(f.x);
                Asm[tid * AP + 4 * c + 1] = f2tf32(f.y);
                Asm[tid * AP + 4 * c + 2] = f2tf32(f.z);
                Asm[tid * AP + 4 * c + 3] = f2tf32(f.w);
            }
            float4 z = make_float4(0.f, 0.f, 0.f, 0.f);
            #pragma unroll
            for (int c = 0; c < 4; c++) aggp[c] = z;
            g_deg[n] = 0.0f;
        } else {
            float dg = g_deg[n];
            dg = dg > 1.0f ? dg : 1.0f;
            const float4* rtp = reinterpret_cast<const float4*>(g_rt + (size_t)n * 16);
            #pragma unroll
            for (int c = 0; c < 4; c++) {
                float4 ag = (n < N) ? aggp[c] : make_float4(0.f, 0.f, 0.f, 0.f);
                float4 rt = (n < N) ? rtp[c] : make_float4(0.f, 0.f, 0.f, 0.f);
                float h0 = ag.x / dg + rt.x; h0 = h0 > 0.f ? h0 : 0.f;
                float h1 = ag.y / dg + rt.y; h1 = h1 > 0.f ? h1 : 0.f;
                float h2 = ag.z / dg + rt.z; h2 = h2 > 0.f ? h2 : 0.f;
                float h3 = ag.w / dg + rt.w; h3 = h3 > 0.f ? h3 : 0.f;
                Asm[tid * AP + 4 * c]     = f2tf32(h0);
                Asm[tid * AP + 4 * c + 1] = f2tf32(h1);
                Asm[tid * AP + 4 * c + 2] = f2tf32(h2);
                Asm[tid * AP + 4 * c + 3] = f2tf32(h3);
            }
            float4 z = make_float4(0.f, 0.f, 0.f, 0.f);
            #pragma unroll
            for (int c = 0; c < 4; c++) aggp[c] = z;
        }
    }
    __syncthreads();

    // A fragments for this warp's 16 rows: [kstep][4]
    uint32_t a[KSTEPS][4];
    {
        int r0 = wid * 16 + gID;
        #pragma unroll
        for (int ks = 0; ks < KSTEPS; ks++) {
            a[ks][0] = Asm[r0 * AP + ks * 8 + tig];
            a[ks][1] = Asm[(r0 + 8) * AP + ks * 8 + tig];
            a[ks][2] = Asm[r0 * AP + ks * 8 + tig + 4];
            a[ks][3] = Asm[(r0 + 8) * AP + ks * 8 + tig + 4];
        }
    }

    #pragma unroll 1
    for (int chunk = 0; chunk < 13; chunk++) {
        if (chunk + 1 < 13) {
            constexpr int NLD = CHUNK_U32 / 4;
            uint32_t dstS = bbase + ((chunk + 1) & 1) * (CHUNK_U32 * 4);
            const char* srcG = (const char*)(Bg + (size_t)(chunk + 1) * CHUNK_U32);
            for (int i = tid; i < NLD; i += 256)
                cp_async16(dstS + i * 16, srcG + i * 16);
        }
        CP_COMMIT();
        CP_WAIT1();
        __syncthreads();

        const uint32_t* bb = Bbuf + (chunk & 1) * CHUNK_U32;
        float c[4][4];
        #pragma unroll
        for (int nt = 0; nt < 4; nt++)
            #pragma unroll
            for (int r = 0; r < 4; r++) c[nt][r] = 0.0f;

        #pragma unroll
        for (int ks = 0; ks < KSTEPS; ks++)
            #pragma unroll
            for (int nt = 0; nt < 4; nt++) {
                uint2 b = *reinterpret_cast<const uint2*>(bb + (nt * KSTEPS + ks) * 64 + lane * 2);
                mma_tf32(c[nt], a[ks], b.x, b.y);
            }
        __syncthreads();  // all warps done with this buffer before re-fill

        // Epilogue for this chunk.
        #pragma unroll
        for (int nt = 0; nt < 4; nt++) {
            int col = chunk * 32 + nt * 8 + tig * 2;
            int row0 = n0 + wid * 16 + gID;
            int row1 = row0 + 8;
            float* cc = c[nt];
            if (col < 400) {
                if (row0 < N)
                    *reinterpret_cast<__half2*>(g_y + (size_t)row0 * 400 + col) =
                        __floats2half2_rn(cc[0], cc[1]);
                if (row1 < N)
                    *reinterpret_cast<__half2*>(g_y + (size_t)row1 * 400 + col) =
                        __floats2half2_rn(cc[2], cc[3]);
            } else {
                int o = col - 400;
                float bv0 = __ldg(bias + o), bv1 = __ldg(bias + o + 1);
                if (row0 < N) {
                    g_rt[(size_t)row0 * 16 + o] = cc[0] + bv0;
                    g_rt[(size_t)row0 * 16 + o + 1] = cc[1] + bv1;
                }
                if (row1 < N) {
                    g_rt[(size_t)row1 * 16 + o] = cc[2] + bv0;
                    g_rt[(size_t)row1 * 16 + o + 1] = cc[3] + bv1;
                }
            }
        }
    }
}

// ---------------- edge kernel (2 lanes/edge) ----------------
__global__ void edge_kernel(const int* __restrict__ src, const int* __restrict__ dst,
                            const float* __restrict__ pseudo, int E, int addDeg) {
    int t = blockIdx.x * blockDim.x + threadIdx.x;
    int e = t >> 1;
    if (e >= E) return;
    int q = t & 1;
    int s = __ldg(src + e);
    int d = __ldg(dst + e);
    float2 p = __ldg(reinterpret_cast<const float2*>(pseudo) + e);
    float v0 = p.x * 4.0f, v1 = p.y * 4.0f;
    float fl0 = floorf(v0), fl1 = floorf(v1);
    float f0 = v0 - fl0, f1 = v1 - fl1;
    int i0 = (int)fl0, i1 = (int)fl1;
    int i0b = i0 + 1; if (i0b >= 5) i0b = 0;
    int i1b = i1 + 1; if (i1b >= 5) i1b = 0;
    float g0 = 1.0f - f0, g1 = 1.0f - f1;
    float w00 = g0 * g1, w10 = f0 * g1, w01 = g0 * f1, w11 = f0 * f1;

    const uint4* yb = reinterpret_cast<const uint4*>(g_y + (size_t)s * 400);
    uint4 c00 = __ldg(yb + ((i1  * 5 + i0 ) * 2 + q));
    uint4 c10 = __ldg(yb + ((i1  * 5 + i0b) * 2 + q));
    uint4 c01 = __ldg(yb + ((i1b * 5 + i0 ) * 2 + q));
    uint4 c11 = __ldg(yb + ((i1b * 5 + i0b) * 2 + q));

    float m[8];
    #pragma unroll
    for (int j = 0; j < 4; j++) {
        float2 a = __half22float2(*reinterpret_cast<const __half2*>(((const unsigned*)&c00) + j));
        float2 b = __half22float2(*reinterpret_cast<const __half2*>(((const unsigned*)&c10) + j));
        float2 c = __half22float2(*reinterpret_cast<const __half2*>(((const unsigned*)&c01) + j));
        float2 dd = __half22float2(*reinterpret_cast<const __half2*>(((const unsigned*)&c11) + j));
        m[2 * j + 0] = w00 * a.x + w10 * b.x + w01 * c.x + w11 * dd.x;
        m[2 * j + 1] = w00 * a.y + w10 * b.y + w01 * c.y + w11 * dd.y;
    }

    float* ap = g_agg + (size_t)d * 16 + q * 8;
    red_add_v4(ap,     m[0], m[1], m[2], m[3]);
    red_add_v4(ap + 4, m[4], m[5], m[6], m[7]);
    if (addDeg && q == 0) atomicAdd(g_deg + d, 1.0f);
}

// Final output: out = agg/max(deg,1) + rt  (float4-vectorized)
__global__ void node_final_kernel(float* __restrict__ out, int N) {
    int i = blockIdx.x * blockDim.x + threadIdx.x;   // float4 group index
    if (i >= N * 4) return;
    float dg = g_deg[i >> 2];
    dg = dg > 1.0f ? dg : 1.0f;
    float4 ag = reinterpret_cast<const float4*>(g_agg)[i];
    float4 rt = reinterpret_cast<const float4*>(g_rt)[i];
    float4 o;
    o.x = ag.x / dg + rt.x;
    o.y = ag.y / dg + rt.y;
    o.z = ag.z / dg + rt.z;
    o.w = ag.w / dg + rt.w;
    reinterpret_cast<float4*>(out)[i] = o;
}

extern "C" void kernel_launch(void* const* d_in, const int* in_sizes, int n_in,
                              void* d_out, int out_size) {
    const float* x      = (const float*)d_in[0];
    const int*   ei     = (const int*)  d_in[1];
    const float* pseudo = (const float*)d_in[2];
    const float* W1     = (const float*)d_in[3];
    const float* root1  = (const float*)d_in[4];
    const float* b1     = (const float*)d_in[5];
    const float* W2     = (const float*)d_in[6];
    const float* root2  = (const float*)d_in[7];
    const float* b2     = (const float*)d_in[8];
    float* out = (float*)d_out;

    int N = in_sizes[0] / 64;
    int E = in_sizes[1] / 2;
    if (N > NCAP) N = NCAP;
    const int* src = ei;
    const int* dst = ei + E;

    // smem: layer1 = 128*68*4 + 2*2048*4 = 51200; layer2 = 128*20*4 + 2*512*4 = 14336
    const int smem1 = 51200, smem2 = 14336;
    static uint32_t *B1p = nullptr, *B2p = nullptr;
    if (!B1p) {
        cudaGetSymbolAddress((void**)&B1p, g_B1);
        cudaGetSymbolAddress((void**)&B2p, g_B2);
        cudaFuncSetAttribute((const void*)gemm_kernel<1, 8>,
                             cudaFuncAttributeMaxDynamicSharedMemorySize, smem1);
        cudaFuncSetAttribute((const void*)gemm_kernel<2, 2>,
                             cudaFuncAttributeMaxDynamicSharedMemorySize, smem2);
    }

    int nodeGrid = (N * 4 + 255) / 256;
    int edgeGrid = (E * 2 + 255) / 256;
    int gemmGrid = (N + 127) / 128;

    prepB_kernel<64, 8><<<(52 * 8 * 64 + 255) / 256, 256>>>(W1, root1, B1p);
    prepB_kernel<16, 2><<<(52 * 2 * 64 + 255) / 256, 256>>>(W2, root2, B2p);
    // ---- Layer 1 (gemm zeroes agg+deg for edge pass 1) ----
    gemm_kernel<1, 8><<<gemmGrid, 256, smem1>>>(x, B1p, b1, N);
    edge_kernel<<<edgeGrid, 256>>>(src, dst, pseudo, E, 1);
    // ---- Layer 2 (gemm consumes layer-1 agg inline, re-zeroes agg) ----
    gemm_kernel<2, 2><<<gemmGrid, 256, smem2>>>(nullptr, B2p, b2, N);
    edge_kernel<<<edgeGrid, 256>>>(src, dst, pseudo, E, 0);
    node_final_kernel<<<nodeGrid, 256>>>(out, N);
}

// round 10
// speedup vs baseline: 1.4354x; 1.1415x over previous
#include <cuda_runtime.h>
#include <cuda_fp16.h>
#include <math.h>
#include <stdint.h>

// Problem constants: N=100000, E=1600000, Cin=64, H=16, Cout=16, K=5
#define NCAP 100096   // multiple of 128

// Scratch (allocation-free contract).
__device__ __half g_y[(size_t)NCAP * 400];               // per-kernel products, fp16
__device__ __align__(32) __half g_agg[(size_t)NCAP * 16]; // per-layer aggregation (fp16 RED target)
__device__ float  g_deg[NCAP];                            // in-degree
__device__ float  g_rt[(size_t)NCAP * 16];                // x @ root + bias (per layer)
// B in tf32 fragment layout: [ntile(52)][kstep][lane(32)*2] u32
__device__ uint32_t g_B1[52 * 8 * 64];
__device__ uint32_t g_B2[52 * 2 * 64];

__device__ __forceinline__ void red_add_v4h2(__half* a, uint32_t h0, uint32_t h1,
                                             uint32_t h2, uint32_t h3) {
    asm volatile("red.global.add.noftz.v4.f16x2 [%0], {%1, %2, %3, %4};"
                 :: "l"(a), "r"(h0), "r"(h1), "r"(h2), "r"(h3) : "memory");
}
__device__ __forceinline__ uint32_t f2tf32(float f) {
    uint32_t o;
    asm("cvt.rna.tf32.f32 %0, %1;" : "=r"(o) : "f"(f));
    return o;
}
__device__ __forceinline__ void mma_tf32(float* c, const uint32_t* a, uint32_t b0, uint32_t b1) {
    asm volatile("mma.sync.aligned.m16n8k8.row.col.f32.tf32.tf32.f32 "
                 "{%0,%1,%2,%3}, {%4,%5,%6,%7}, {%8,%9}, {%0,%1,%2,%3};"
                 : "+f"(c[0]), "+f"(c[1]), "+f"(c[2]), "+f"(c[3])
                 : "r"(a[0]), "r"(a[1]), "r"(a[2]), "r"(a[3]), "r"(b0), "r"(b1));
}
__device__ __forceinline__ void cp_async16(uint32_t saddr, const void* g) {
    asm volatile("cp.async.cg.shared.global [%0], [%1], 16;" :: "r"(saddr), "l"(g));
}
#define CP_COMMIT() asm volatile("cp.async.commit_group;" ::: "memory")
#define CP_WAIT1()  asm volatile("cp.async.wait_group 1;" ::: "memory")
__device__ __forceinline__ uint32_t smem_u32(const void* p) {
    uint32_t a;
    asm("{ .reg .u64 t; cvta.to.shared.u64 t, %1; cvt.u32.u64 %0, t; }" : "=r"(a) : "l"(p));
    return a;
}

// Build tf32 B fragments. Logical B[n=0..415][k]: n<400 -> W[(kk*CIN+k)*16+o]
// (kk=n>>4, o=n&15); n>=400 -> root[k*16+(n-400)].
template<int CIN, int KSTEPS>
__global__ void prepB_kernel(const float* __restrict__ W, const float* __restrict__ root,
                             uint32_t* __restrict__ Bg) {
    int idx = blockIdx.x * blockDim.x + threadIdx.x;
    if (idx >= 52 * KSTEPS * 64) return;
    int ntile = idx / (KSTEPS * 64);
    int rem = idx % (KSTEPS * 64);
    int ks = rem / 64;
    int q = rem % 64;
    int lane = q >> 1;
    int reg = q & 1;
    int n = ntile * 8 + (lane >> 2);
    int k = ks * 8 + (lane & 3) + reg * 4;
    float v = 0.0f;
    if (k < CIN) {
        if (n < 400) {
            int kk = n >> 4, o = n & 15;
            v = W[(kk * CIN + k) * 16 + o];
        } else {
            v = root[k * 16 + (n - 400)];
        }
    }
    Bg[idx] = f2tf32(v);
}

// HMMA tf32 GEMM + fusions. Per CTA: M=128 nodes, N=416; 256 threads, 8 warps,
// one m16 tile per warp. 3-stage cp.async ring, ONE barrier per chunk.
// LAYER=1: A = Xin; also zero g_agg (fp16) + g_deg for its rows.
// LAYER=2: A = relu(agg/max(deg,1) + rt) inline; then re-zero g_agg.
template<int LAYER, int KSTEPS>
__global__ void __launch_bounds__(256) gemm_kernel(const float* __restrict__ Xin,
                                                   const uint32_t* __restrict__ Bg,
                                                   const float* __restrict__ bias, int N) {
    constexpr int KC = KSTEPS * 8;          // real K (64 or 16)
    constexpr int AP = KC + 4;              // A row pitch (u32)
    constexpr int CHUNK_U32 = 4 * KSTEPS * 64;
    constexpr int NLD = CHUNK_U32 / 4;      // 16B loads per chunk
    extern __shared__ uint32_t sm[];
    uint32_t* Asm = sm;                      // [128][AP]
    uint32_t* Bbuf = sm + 128 * AP;          // [3][CHUNK_U32]
    const uint32_t bbase = smem_u32(Bbuf);

    const int tid = threadIdx.x;
    const int wid = tid >> 5;
    const int lane = tid & 31;
    const int gID = lane >> 2;
    const int tig = lane & 3;
    const int n0 = blockIdx.x * 128;

    // Prologue: issue chunks 0 and 1 into ring slots 0, 1.
    for (int i = tid; i < NLD; i += 256)
        cp_async16(bbase + i * 16, (const char*)Bg + i * 16);
    CP_COMMIT();
    for (int i = tid; i < NLD; i += 256)
        cp_async16(bbase + CHUNK_U32 * 4 + i * 16,
                   (const char*)(Bg + CHUNK_U32) + i * 16);
    CP_COMMIT();

    // Threads 0..127 each own row n0+tid: build A row + fused per-node work.
    if (tid < 128) {
        const int n = n0 + tid;
        uint4* aggp = reinterpret_cast<uint4*>(g_agg + (size_t)n * 16);  // 32B row
        if (LAYER == 1) {
            const float4* xr = reinterpret_cast<const float4*>(Xin + (size_t)n * 64);
            #pragma unroll
            for (int c = 0; c < KC / 4; c++) {
                float4 f = (n < N) ? __ldg(xr + c) : make_float4(0.f, 0.f, 0.f, 0.f);
                Asm[tid * AP + 4 * c]     = f2tf32(f.x);
                Asm[tid * AP + 4 * c + 1] = f2tf32(f.y);
                Asm[tid * AP + 4 * c + 2] = f2tf32(f.z);
                Asm[tid * AP + 4 * c + 3] = f2tf32(f.w);
            }
            uint4 z = make_uint4(0u, 0u, 0u, 0u);
            aggp[0] = z; aggp[1] = z;
            g_deg[n] = 0.0f;
        } else {
            float dg = g_deg[n];
            dg = dg > 1.0f ? dg : 1.0f;
            float inv = 1.0f / dg;
            const float4* rtp = reinterpret_cast<const float4*>(g_rt + (size_t)n * 16);
            const __half2* ah = reinterpret_cast<const __half2*>(g_agg + (size_t)n * 16);
            #pragma unroll
            for (int c = 0; c < 4; c++) {
                float2 a0 = __half22float2(ah[2 * c]);
                float2 a1 = __half22float2(ah[2 * c + 1]);
                float4 rt = (n < N) ? __ldg(rtp + c) : make_float4(0.f, 0.f, 0.f, 0.f);
                float h0 = a0.x * inv + rt.x; h0 = h0 > 0.f ? h0 : 0.f;
                float h1 = a0.y * inv + rt.y; h1 = h1 > 0.f ? h1 : 0.f;
                float h2 = a1.x * inv + rt.z; h2 = h2 > 0.f ? h2 : 0.f;
                float h3 = a1.y * inv + rt.w; h3 = h3 > 0.f ? h3 : 0.f;
                Asm[tid * AP + 4 * c]     = f2tf32(h0);
                Asm[tid * AP + 4 * c + 1] = f2tf32(h1);
                Asm[tid * AP + 4 * c + 2] = f2tf32(h2);
                Asm[tid * AP + 4 * c + 3] = f2tf32(h3);
            }
            uint4 z = make_uint4(0u, 0u, 0u, 0u);
            aggp[0] = z; aggp[1] = z;
        }
    }
    __syncthreads();

    // A fragments for this warp's 16 rows: [kstep][4]
    uint32_t a[KSTEPS][4];
    {
        int r0 = wid * 16 + gID;
        #pragma unroll
        for (int ks = 0; ks < KSTEPS; ks++) {
            a[ks][0] = Asm[r0 * AP + ks * 8 + tig];
            a[ks][1] = Asm[(r0 + 8) * AP + ks * 8 + tig];
            a[ks][2] = Asm[r0 * AP + ks * 8 + tig + 4];
            a[ks][3] = Asm[(r0 + 8) * AP + ks * 8 + tig + 4];
        }
    }

    #pragma unroll 1
    for (int chunk = 0; chunk < 13; chunk++) {
        CP_WAIT1();          // chunk's group complete (<=1 younger outstanding)
        __syncthreads();     // all threads' portions visible

        const uint32_t* bb = Bbuf + (chunk % 3) * CHUNK_U32;
        float c[4][4];
        #pragma unroll
        for (int nt = 0; nt < 4; nt++)
            #pragma unroll
            for (int r = 0; r < 4; r++) c[nt][r] = 0.0f;

        #pragma unroll
        for (int ks = 0; ks < KSTEPS; ks++)
            #pragma unroll
            for (int nt = 0; nt < 4; nt++) {
                uint2 b = *reinterpret_cast<const uint2*>(bb + (nt * KSTEPS + ks) * 64 + lane * 2);
                mma_tf32(c[nt], a[ks], b.x, b.y);
            }

        // Epilogue for this chunk.
        #pragma unroll
        for (int nt = 0; nt < 4; nt++) {
            int col = chunk * 32 + nt * 8 + tig * 2;
            int row0 = n0 + wid * 16 + gID;
            int row1 = row0 + 8;
            float* cc = c[nt];
            if (col < 400) {
                if (row0 < N)
                    *reinterpret_cast<__half2*>(g_y + (size_t)row0 * 400 + col) =
                        __floats2half2_rn(cc[0], cc[1]);
                if (row1 < N)
                    *reinterpret_cast<__half2*>(g_y + (size_t)row1 * 400 + col) =
                        __floats2half2_rn(cc[2], cc[3]);
            } else {
                int o = col - 400;
                float bv0 = __ldg(bias + o), bv1 = __ldg(bias + o + 1);
                if (row0 < N) {
                    g_rt[(size_t)row0 * 16 + o] = cc[0] + bv0;
                    g_rt[(size_t)row0 * 16 + o + 1] = cc[1] + bv1;
                }
                if (row1 < N) {
                    g_rt[(size_t)row1 * 16 + o] = cc[2] + bv0;
                    g_rt[(size_t)row1 * 16 + o + 1] = cc[3] + bv1;
                }
            }
        }

        // Issue chunk+2 into ring slot (chunk+2)%3. Safe: every thread passed the
        // barrier for this chunk, so all compute on slot (chunk+2)%3 == (chunk-1)%3
        // finished before any thread can issue into it.
        if (chunk + 2 < 13) {
            uint32_t dstS = bbase + ((chunk + 2) % 3) * (CHUNK_U32 * 4);
            const char* srcG = (const char*)(Bg + (size_t)(chunk + 2) * CHUNK_U32);
            for (int i = tid; i < NLD; i += 256)
                cp_async16(dstS + i * 16, srcG + i * 16);
        }
        CP_COMMIT();         // commit every iter (possibly empty) to keep group math uniform
    }
}

// ---------------- edge kernel (2 lanes/edge, fp16x2 vector RED) ----------------
__global__ void edge_kernel(const int* __restrict__ src, const int* __restrict__ dst,
                            const float* __restrict__ pseudo, int E, int addDeg) {
    int t = blockIdx.x * blockDim.x + threadIdx.x;
    int e = t >> 1;
    if (e >= E) return;
    int q = t & 1;
    int s = __ldg(src + e);
    int d = __ldg(dst + e);
    float2 p = __ldg(reinterpret_cast<const float2*>(pseudo) + e);
    float v0 = p.x * 4.0f, v1 = p.y * 4.0f;
    float fl0 = floorf(v0), fl1 = floorf(v1);
    float f0 = v0 - fl0, f1 = v1 - fl1;
    int i0 = (int)fl0, i1 = (int)fl1;
    int i0b = i0 + 1; if (i0b >= 5) i0b = 0;
    int i1b = i1 + 1; if (i1b >= 5) i1b = 0;
    float g0 = 1.0f - f0, g1 = 1.0f - f1;
    float w00 = g0 * g1, w10 = f0 * g1, w01 = g0 * f1, w11 = f0 * f1;

    const uint4* yb = reinterpret_cast<const uint4*>(g_y + (size_t)s * 400);
    uint4 c00 = __ldg(yb + ((i1  * 5 + i0 ) * 2 + q));
    uint4 c10 = __ldg(yb + ((i1  * 5 + i0b) * 2 + q));
    uint4 c01 = __ldg(yb + ((i1b * 5 + i0 ) * 2 + q));
    uint4 c11 = __ldg(yb + ((i1b * 5 + i0b) * 2 + q));

    uint32_t hm[4];
    #pragma unroll
    for (int j = 0; j < 4; j++) {
        float2 a = __half22float2(*reinterpret_cast<const __half2*>(((const unsigned*)&c00) + j));
        float2 b = __half22float2(*reinterpret_cast<const __half2*>(((const unsigned*)&c10) + j));
        float2 c = __half22float2(*reinterpret_cast<const __half2*>(((const unsigned*)&c01) + j));
        float2 dd = __half22float2(*reinterpret_cast<const __half2*>(((const unsigned*)&c11) + j));
        float mx = w00 * a.x + w10 * b.x + w01 * c.x + w11 * dd.x;
        float my = w00 * a.y + w10 * b.y + w01 * c.y + w11 * dd.y;
        __half2 h = __floats2half2_rn(mx, my);
        hm[j] = *reinterpret_cast<uint32_t*>(&h);
    }

    red_add_v4h2(g_agg + (size_t)d * 16 + q * 8, hm[0], hm[1], hm[2], hm[3]);
    if (addDeg && q == 0) atomicAdd(g_deg + d, 1.0f);
}

// Final output: out = agg/max(deg,1) + rt  (float4-vectorized, agg is fp16)
__global__ void node_final_kernel(float* __restrict__ out, int N) {
    int i = blockIdx.x * blockDim.x + threadIdx.x;   // float4 group index
    if (i >= N * 4) return;
    float dg = g_deg[i >> 2];
    dg = dg > 1.0f ? dg : 1.0f;
    float inv = 1.0f / dg;
    const __half2* ah = reinterpret_cast<const __half2*>(g_agg) + i * 2;
    float2 a0 = __half22float2(ah[0]);
    float2 a1 = __half22float2(ah[1]);
    float4 rt = reinterpret_cast<const float4*>(g_rt)[i];
    float4 o;
    o.x = a0.x * inv + rt.x;
    o.y = a0.y * inv + rt.y;
    o.z = a1.x * inv + rt.z;
    o.w = a1.y * inv + rt.w;
    reinterpret_cast<float4*>(out)[i] = o;
}

extern "C" void kernel_launch(void* const* d_in, const int* in_sizes, int n_in,
                              void* d_out, int out_size) {
    const float* x      = (const float*)d_in[0];
    const int*   ei     = (const int*)  d_in[1];
    const float* pseudo = (const float*)d_in[2];
    const float* W1     = (const float*)d_in[3];
    const float* root1  = (const float*)d_in[4];
    const float* b1     = (const float*)d_in[5];
    const float* W2     = (const float*)d_in[6];
    const float* root2  = (const float*)d_in[7];
    const float* b2     = (const float*)d_in[8];
    float* out = (float*)d_out;

    int N = in_sizes[0] / 64;
    int E = in_sizes[1] / 2;
    if (N > NCAP) N = NCAP;
    const int* src = ei;
    const int* dst = ei + E;

    // smem: layer1 = 128*68*4 + 3*2048*4 = 34816+24576 = 59392
    //       layer2 = 128*20*4 + 3*512*4 = 10240+6144  = 16384
    const int smem1 = 59392, smem2 = 16384;
    static uint32_t *B1p = nullptr, *B2p = nullptr;
    if (!B1p) {
        cudaGetSymbolAddress((void**)&B1p, g_B1);
        cudaGetSymbolAddress((void**)&B2p, g_B2);
        cudaFuncSetAttribute((const void*)gemm_kernel<1, 8>,
                             cudaFuncAttributeMaxDynamicSharedMemorySize, smem1);
        cudaFuncSetAttribute((const void*)gemm_kernel<2, 2>,
                             cudaFuncAttributeMaxDynamicSharedMemorySize, smem2);
    }

    int nodeGrid = (N * 4 + 255) / 256;
    int edgeGrid = (E * 2 + 255) / 256;
    int gemmGrid = (N + 127) / 128;

    prepB_kernel<64, 8><<<(52 * 8 * 64 + 255) / 256, 256>>>(W1, root1, B1p);
    prepB_kernel<16, 2><<<(52 * 2 * 64 + 255) / 256, 256>>>(W2, root2, B2p);
    // ---- Layer 1 (gemm zeroes agg+deg for edge pass 1) ----
    gemm_kernel<1, 8><<<gemmGrid, 256, smem1>>>(x, B1p, b1, N);
    edge_kernel<<<edgeGrid, 256>>>(src, dst, pseudo, E, 1);
    // ---- Layer 2 (gemm consumes layer-1 agg inline, re-zeroes agg) ----
    gemm_kernel<2, 2><<<gemmGrid, 256, smem2>>>(nullptr, B2p, b2, N);
    edge_kernel<<<edgeGrid, 256>>>(src, dst, pseudo, E, 0);
    node_final_kernel<<<nodeGrid, 256>>>(out, N);
}